// round 14
// baseline (speedup 1.0000x reference)
#include <cuda_runtime.h>
#include <cstdint>

#define B_ 64
#define T_ 128
#define E_ 512
#define U_ 1024
#define G_ 3072          // 3*U
#define SGST 68          // sG row stride (floats)
#define HID_OFF (B_*T_*U_)

typedef unsigned long long ull;

// ---------------- device scratch (static, allocation-free) ----------------
__device__ __align__(256) float d_XT[T_][E_][B_];       // emb(tokens), [t_orig][e][b]
__device__ __align__(256) float d_xg[2][T_][G_][B_];    // input projections per scan step
__device__ __align__(256) float d_outs[2][T_][U_][B_];  // per-dir hidden sequences (= h chain)
__device__ __align__(256) float d_h0[U_][B_];           // zero initial state (both dirs)
__device__ unsigned g_bar;                              // monotonic grid barrier

// ---------------- f32x2 helpers (Blackwell packed fp32) ----------------
__device__ __forceinline__ ull pk2(float v) {
    ull r; asm("mov.b64 %0, {%1, %1};" : "=l"(r) : "f"(v)); return r;
}
__device__ __forceinline__ ull mk2(float lo, float hi) {
    ull r; asm("mov.b64 %0, {%1, %2};" : "=l"(r) : "f"(lo), "f"(hi)); return r;
}
__device__ __forceinline__ void unpk2(ull v, float& lo, float& hi) {
    asm("mov.b64 {%0, %1}, %2;" : "=f"(lo), "=f"(hi) : "l"(v));
}
__device__ __forceinline__ void fma2(ull& d, ull a, ull b) {
    asm("fma.rn.f32x2 %0, %1, %2, %0;" : "+l"(d) : "l"(a), "l"(b));
}
__device__ __forceinline__ ull add2(ull a, ull b) {
    ull r; asm("add.rn.f32x2 %0, %1, %2;" : "=l"(r) : "l"(a), "l"(b)); return r;
}
__device__ __forceinline__ float sigf(float x) { return 1.0f / (1.0f + __expf(-x)); }

union F4 { float4 v; float f[4]; ull u[2]; };
union F2 { float2 v; float f[2]; };

// ---------------- init: zero h0, reset barrier ----------------
__global__ void k_init() {
    int n = U_ * B_;
    float* p = &d_h0[0][0];
    for (int i = blockIdx.x * blockDim.x + threadIdx.x; i < n; i += gridDim.x * blockDim.x)
        p[i] = 0.0f;
    if (blockIdx.x == 0 && threadIdx.x == 0) g_bar = 0u;
}

// ---------------- embedding gather (transposed store) ----------------
__global__ void k_embed(const int* __restrict__ tokens, const float* __restrict__ emb) {
    int t = blockIdx.x;
    int b = threadIdx.x & 63;
    int sub = threadIdx.x >> 6;
    int tok = tokens[b * T_ + t];
    const float* er = emb + (size_t)tok * E_;
    for (int e = sub; e < E_; e += 4)
        d_XT[t][e][b] = er[e];
}

// ---------------- input projection GEMM (unchanged, passing) ----------------
__global__ void __launch_bounds__(128) k_gemm_in(const float* __restrict__ Wf,
                                                 const float* __restrict__ Wb,
                                                 const float* __restrict__ bif,
                                                 const float* __restrict__ bib) {
    int gt = blockIdx.x, s = blockIdx.y, dir = blockIdx.z;
    int g0 = gt * 48;
    int torig = dir ? s : (T_ - 1 - s);
    const float* W  = dir ? Wb  : Wf;
    const float* bi = dir ? bib : bif;

    __shared__ __align__(16) float sW[64 * 48];
    __shared__ __align__(16) float sA[64 * 64];

    int tid = threadIdx.x;
    int kh = tid >> 6, r = tid & 63, cg = r >> 3, bg = r & 7;
    int b0 = bg << 3, c0 = cg * 6;

    ull acc[6][4];
#pragma unroll
    for (int j = 0; j < 6; j++) {
        ull init = kh ? 0ull : pk2(bi[g0 + c0 + j]);
#pragma unroll
        for (int p = 0; p < 4; p++) acc[j][p] = init;
    }

    for (int kc = 0; kc < E_ / 64; kc++) {
        __syncthreads();
        for (int idx = tid; idx < 64 * 48; idx += 128) {
            int kk = idx / 48, c = idx - kk * 48;
            sW[idx] = W[(size_t)(kc * 64 + kk) * G_ + g0 + c];
        }
        const float4* src = (const float4*)(&d_XT[torig][kc * 64][0]);
        float4* dst = (float4*)sA;
#pragma unroll
        for (int i = 0; i < 8; i++) dst[tid + i * 128] = src[tid + i * 128];
        __syncthreads();

        const float* hb  = sA + (kh * 32) * 64;
        const float* wb_ = sW + (kh * 32) * 48;
#pragma unroll 4
        for (int kk = 0; kk < 32; kk++) {
            ull hp[4];
#pragma unroll
            for (int p = 0; p < 4; p++) hp[p] = *(const ull*)(hb + kk * 64 + b0 + 2 * p);
#pragma unroll
            for (int j = 0; j < 6; j++) {
                ull us = pk2(wb_[kk * 48 + c0 + j]);
#pragma unroll
                for (int p = 0; p < 4; p++) fma2(acc[j][p], hp[p], us);
            }
        }
    }
    __syncthreads();
    ull* part = (ull*)sA;
    if (kh) {
#pragma unroll
        for (int j = 0; j < 6; j++)
#pragma unroll
            for (int p = 0; p < 4; p++) part[r * 24 + j * 4 + p] = acc[j][p];
    }
    __syncthreads();
    if (!kh) {
#pragma unroll
        for (int j = 0; j < 6; j++) {
#pragma unroll
            for (int q = 0; q < 2; q++) {
                F4 o;
                o.u[0] = add2(acc[j][2 * q + 0], part[r * 24 + j * 4 + 2 * q + 0]);
                o.u[1] = add2(acc[j][2 * q + 1], part[r * 24 + j * 4 + 2 * q + 1]);
                *(float4*)(&d_xg[dir][s][g0 + c0 + j][b0 + 4 * q]) = o.v;
            }
        }
    }
}

// ---------------- persistent recurrent kernel ----------------
// R14: weights smem-resident in k-pair-interleaved layout [kp][c][2] ->
// 3 conflict-free LDS.128 per TWO k-rows (halves LDS count vs R11).
// h read from L2 via one LDG.128 per k-row ([k][b] layout, R11's shape).
// acc[6][4] f32x2 with k-parity lanes; collapse lo+hi once per step.
__global__ void __launch_bounds__(512, 1) k_rec(const float* __restrict__ Uf,
                                                const float* __restrict__ Ub,
                                                const float* __restrict__ bhf,
                                                const float* __restrict__ bhb) {
    extern __shared__ __align__(16) float smem[];
    float* sU = smem;                // 48*1024 floats = 196608 B, layout [kp][c][2]
    float* sS = smem + 48 * 1024;    // 8192 floats scratch: P0 [0,3072), sG aliases [3072,6336)

    int dir = blockIdx.x >> 6;
    int uc  = blockIdx.x & 63;
    int u0  = uc << 4;
    const float* Uw = dir ? Ub : Uf;
    const float* bh = dir ? bhb : bhf;
    int tid = threadIdx.x;
    unsigned nCTA = gridDim.x;

    // one-time: Uw slice -> sU[kp][c][2]; element (k,c) at kp*96 + c*2 + (k&1)
    for (int idx = tid; idx < 48 * 1024; idx += 512) {
        int kp = idx / 96, rem = idx - kp * 96;
        int c = rem >> 1, kb = rem & 1;
        int k = 2 * kp + kb;
        sU[idx] = Uw[(size_t)k * G_ + (c >> 4) * U_ + u0 + (c & 15)];
    }

    int kh = tid >> 7;                 // 0..3: k quarter; kp range [kh*128, kh*128+128)
    int r  = tid & 127;
    int cg = r & 7, bg = r >> 3;       // 8 cgs x 16 bgs
    int c0 = cg * 6, b0 = bg * 4;

    // bias (kh0 only): lanes (bias, 0) so lo+hi collapse adds it once
    ull binit[6];
#pragma unroll
    for (int j = 0; j < 6; j++) {
        if (kh) { binit[j] = 0ull; continue; }
        int c = c0 + j;
        binit[j] = mk2(bh[(c >> 4) * U_ + u0 + (c & 15)], 0.0f);
    }

    // epilogue mapping: 512 tasks of (u, 2b); warp covers one u-row of 64 b
    int eu = tid >> 5;                 // 0..15
    int eb = (tid & 31) * 2;           // 0..62
    int gu = u0 + eu;
    const float* xgbase = &d_xg[dir][0][0][0];
    const float* ubB = sU + (size_t)(kh * 128) * 96 + c0 * 2;

    __syncthreads();                   // sU resident

    for (int s = 0; s < T_; s++) {
        const float* hprev = (s == 0) ? &d_h0[0][0] : &d_outs[dir][s - 1][0][0];
        const float* hb = hprev + (size_t)(kh * 256) * 64 + b0;

        // prefetch epilogue operands (consumed after the mainloop)
        const float* xs = xgbase + (size_t)s * G_ * B_;
        F2 xz, xr, xh, hpv;
        xz.v  = *(const float2*)(xs + (size_t)gu * B_ + eb);
        xr.v  = *(const float2*)(xs + (size_t)(U_ + gu) * B_ + eb);
        xh.v  = *(const float2*)(xs + (size_t)(2 * U_ + gu) * B_ + eb);
        hpv.v = __ldcg((const float2*)(hprev + (size_t)gu * B_ + eb));

        ull acc[6][4];
#pragma unroll
        for (int j = 0; j < 6; j++)
#pragma unroll
            for (int b = 0; b < 4; b++) acc[j][b] = binit[j];

        // mainloop: 128 kp (2 k-rows each); 1-kp LDG lookahead; zero barriers
        F4 ea, eo, na, no;
        ea.v = __ldcg((const float4*)(hb + 0 * 64));
        eo.v = __ldcg((const float4*)(hb + 1 * 64));
        na.v = __ldcg((const float4*)(hb + 2 * 64));
        no.v = __ldcg((const float4*)(hb + 3 * 64));
#pragma unroll 2
        for (int kp = 0; kp < 128; kp++) {
            F4 fa, fo;
            int gn = (kp < 126) ? (2 * kp + 4) : 252;
            fa.v = __ldcg((const float4*)(hb + (size_t)gn * 64));
            fo.v = __ldcg((const float4*)(hb + (size_t)(gn + 1) * 64));

            const float* wp = ubB + (size_t)kp * 96;
            F4 q0, q1, q2;
            q0.v = *(const float4*)(wp);        // cols c0,c0+1  x (ke,ko)
            q1.v = *(const float4*)(wp + 4);    // cols c0+2,c0+3
            q2.v = *(const float4*)(wp + 8);    // cols c0+4,c0+5

            ull hp0 = mk2(ea.f[0], eo.f[0]);
            ull hp1 = mk2(ea.f[1], eo.f[1]);
            ull hp2 = mk2(ea.f[2], eo.f[2]);
            ull hp3 = mk2(ea.f[3], eo.f[3]);

            fma2(acc[0][0], hp0, q0.u[0]); fma2(acc[0][1], hp1, q0.u[0]);
            fma2(acc[0][2], hp2, q0.u[0]); fma2(acc[0][3], hp3, q0.u[0]);
            fma2(acc[1][0], hp0, q0.u[1]); fma2(acc[1][1], hp1, q0.u[1]);
            fma2(acc[1][2], hp2, q0.u[1]); fma2(acc[1][3], hp3, q0.u[1]);
            fma2(acc[2][0], hp0, q1.u[0]); fma2(acc[2][1], hp1, q1.u[0]);
            fma2(acc[2][2], hp2, q1.u[0]); fma2(acc[2][3], hp3, q1.u[0]);
            fma2(acc[3][0], hp0, q1.u[1]); fma2(acc[3][1], hp1, q1.u[1]);
            fma2(acc[3][2], hp2, q1.u[1]); fma2(acc[3][3], hp3, q1.u[1]);
            fma2(acc[4][0], hp0, q2.u[0]); fma2(acc[4][1], hp1, q2.u[0]);
            fma2(acc[4][2], hp2, q2.u[0]); fma2(acc[4][3], hp3, q2.u[0]);
            fma2(acc[5][0], hp0, q2.u[1]); fma2(acc[5][1], hp1, q2.u[1]);
            fma2(acc[5][2], hp2, q2.u[1]); fma2(acc[5][3], hp3, q2.u[1]);

            ea = na; eo = no; na = fa; no = fo;
        }

        // collapse k-parity lanes -> float gates gf[6][4]
        float gf[6][4];
#pragma unroll
        for (int j = 0; j < 6; j++)
#pragma unroll
            for (int b = 0; b < 4; b++) {
                float lo, hi; unpk2(acc[j][b], lo, hi);
                gf[j][b] = lo + hi;
            }

        // cross-kh float reduce. P0 = sS[0,3072); sG aliases [3072,6336).
        float* P0 = sS;
        float* sG = sS + 3072;
        if (kh == 2) {
#pragma unroll
            for (int j = 0; j < 6; j++)
#pragma unroll
                for (int b = 0; b < 4; b++) P0[r * 24 + j * 4 + b] = gf[j][b];
        }
        if (kh == 3) {
#pragma unroll
            for (int j = 0; j < 6; j++)
#pragma unroll
                for (int b = 0; b < 4; b++) sG[r * 24 + j * 4 + b] = gf[j][b];
        }
        __syncthreads();
        if (kh == 0) {
#pragma unroll
            for (int j = 0; j < 6; j++)
#pragma unroll
                for (int b = 0; b < 4; b++) gf[j][b] += P0[r * 24 + j * 4 + b];
        }
        if (kh == 1) {
#pragma unroll
            for (int j = 0; j < 6; j++)
#pragma unroll
                for (int b = 0; b < 4; b++) gf[j][b] += sG[r * 24 + j * 4 + b];
        }
        __syncthreads();
        if (kh == 1) {
#pragma unroll
            for (int j = 0; j < 6; j++)
#pragma unroll
                for (int b = 0; b < 4; b++) P0[r * 24 + j * 4 + b] = gf[j][b];
        }
        __syncthreads();
        if (kh == 0) {
#pragma unroll
            for (int j = 0; j < 6; j++)
#pragma unroll
                for (int b = 0; b < 4; b++) {
                    float v = gf[j][b] + P0[r * 24 + j * 4 + b];
                    sG[(c0 + j) * SGST + b0 + b] = v;
                }
        }
        __syncthreads();

        // epilogue: gates -> h_new, one (u, 2b) per thread; single store to d_outs[s]
        {
            F2 hz, hr, hh, hn;
            hz.v = *(float2*)(sG + eu * SGST + eb);
            hr.v = *(float2*)(sG + (16 + eu) * SGST + eb);
            hh.v = *(float2*)(sG + (32 + eu) * SGST + eb);
#pragma unroll
            for (int e = 0; e < 2; e++) {
                float z  = sigf(xz.f[e] + hz.f[e]);
                float rr = sigf(xr.f[e] + hr.f[e]);
                float hc = tanhf(xh.f[e] + rr * hh.f[e]);
                hn.f[e]  = z * hpv.f[e] + (1.0f - z) * hc;
            }
            __stcg((float2*)(&d_outs[dir][s][gu][eb]), hn.v);
        }

        // grid barrier (monotonic; 128 co-resident CTAs)
        __syncthreads();
        if (tid == 0) {
            __threadfence();
            unsigned target = nCTA * (unsigned)(s + 1);
            unsigned v = atomicAdd(&g_bar, 1u) + 1u;
            while (v < target) {
                __nanosleep(128);
                v = atomicAdd(&g_bar, 0u);
            }
            __threadfence();
        }
        __syncthreads();
    }
}

// ---------------- combine: out[b][t][u] = outs_f[t][u][b] + outs_b[T-1-t][u][b] ----------------
__global__ void k_comb(float* __restrict__ out) {
    __shared__ float sT[32][33];
    int t = blockIdx.x, u0 = blockIdx.y * 32, b0 = blockIdx.z * 32;
    int tx = threadIdx.x, ty = threadIdx.y;
#pragma unroll
    for (int i = 0; i < 4; i++) {
        int u = ty + i * 8;
        sT[u][tx] = d_outs[0][t][u0 + u][b0 + tx] + d_outs[1][T_ - 1 - t][u0 + u][b0 + tx];
    }
    __syncthreads();
#pragma unroll
    for (int i = 0; i < 4; i++) {
        int b = ty + i * 8;
        out[((size_t)(b0 + b) * T_ + t) * U_ + u0 + tx] = sT[tx][b];
    }
}

// ---------------- hidden concat ----------------
__global__ void k_hid(float* __restrict__ out) {
    __shared__ float sT[32][33];
    int u0 = blockIdx.x * 32, dir = blockIdx.y, b0 = blockIdx.z * 32;
    int tx = threadIdx.x, ty = threadIdx.y;
#pragma unroll
    for (int i = 0; i < 4; i++) {
        int u = ty + i * 8;
        sT[u][tx] = d_outs[dir][T_ - 1][u0 + u][b0 + tx];
    }
    __syncthreads();
#pragma unroll
    for (int i = 0; i < 4; i++) {
        int b = ty + i * 8;
        out[HID_OFF + (size_t)(b0 + b) * (2 * U_) + dir * U_ + u0 + tx] = sT[tx][b];
    }
}

extern "C" void kernel_launch(void* const* d_in, const int* in_sizes, int n_in,
                              void* d_out, int out_size) {
    const int*   tokens = (const int*)d_in[0];
    const float* emb    = (const float*)d_in[1];
    const float* Wf     = (const float*)d_in[2];
    const float* Uf     = (const float*)d_in[3];
    const float* bif    = (const float*)d_in[4];
    const float* bhf    = (const float*)d_in[5];
    const float* Wb     = (const float*)d_in[6];
    const float* Ub     = (const float*)d_in[7];
    const float* bib    = (const float*)d_in[8];
    const float* bhb    = (const float*)d_in[9];
    float* out = (float*)d_out;

    const int SMEM_REC = (48 * 1024 + 8192) * (int)sizeof(float);  // 229376 B
    cudaFuncSetAttribute(k_rec, cudaFuncAttributeMaxDynamicSharedMemorySize, SMEM_REC);

    k_init<<<64, 256>>>();
    k_embed<<<T_, 256>>>(tokens, emb);
    {
        dim3 g(64, T_, 2);
        k_gemm_in<<<g, 128>>>(Wf, Wb, bif, bib);
    }
    k_rec<<<128, 512, SMEM_REC>>>(Uf, Ub, bhf, bhb);
    {
        dim3 g(T_, U_ / 32, B_ / 32);
        k_comb<<<g, dim3(32, 8)>>>(out);
    }
    {
        dim3 g(U_ / 32, 2, B_ / 32);
        k_hid<<<g, dim3(32, 8)>>>(out);
    }
    (void)in_sizes; (void)n_in; (void)out_size;
}

// round 15
// speedup vs baseline: 1.1641x; 1.1641x over previous
#include <cuda_runtime.h>
#include <cstdint>

#define B_ 64
#define T_ 128
#define E_ 512
#define U_ 1024
#define G_ 3072          // 3*U
#define SGST 68          // sG row stride (floats)
#define HID_OFF (B_*T_*U_)

typedef unsigned long long ull;

// ---------------- device scratch (static, allocation-free) ----------------
__device__ __align__(256) float d_XT[T_][E_][B_];       // emb(tokens), [t_orig][e][b]
__device__ __align__(256) float d_xg[2][T_][G_][B_];    // input projections per scan step
__device__ __align__(256) float d_outs[2][T_][U_][B_];  // per-dir hidden sequences (= h chain)
__device__ __align__(256) float d_h0[U_][B_];           // zero initial state (both dirs)
__device__ unsigned g_bar;                              // monotonic grid barrier

// ---------------- f32x2 helpers (Blackwell packed fp32) ----------------
__device__ __forceinline__ ull pk2(float v) {
    ull r; asm("mov.b64 %0, {%1, %1};" : "=l"(r) : "f"(v)); return r;
}
__device__ __forceinline__ void unpk2(ull v, float& lo, float& hi) {
    asm("mov.b64 {%0, %1}, %2;" : "=f"(lo), "=f"(hi) : "l"(v));
}
__device__ __forceinline__ void fma2(ull& d, ull a, ull b) {
    asm("fma.rn.f32x2 %0, %1, %2, %0;" : "+l"(d) : "l"(a), "l"(b));
}
__device__ __forceinline__ ull add2(ull a, ull b) {
    ull r; asm("add.rn.f32x2 %0, %1, %2;" : "=l"(r) : "l"(a), "l"(b)); return r;
}
__device__ __forceinline__ float sigf(float x) { return 1.0f / (1.0f + __expf(-x)); }

union F4 { float4 v; float f[4]; ull u[2]; };
union F2 { float2 v; float f[2]; };

// ---------------- init: zero h0, reset barrier ----------------
__global__ void k_init() {
    int n = U_ * B_;
    float* p = &d_h0[0][0];
    for (int i = blockIdx.x * blockDim.x + threadIdx.x; i < n; i += gridDim.x * blockDim.x)
        p[i] = 0.0f;
    if (blockIdx.x == 0 && threadIdx.x == 0) g_bar = 0u;
}

// ---------------- embedding gather (transposed store) ----------------
__global__ void k_embed(const int* __restrict__ tokens, const float* __restrict__ emb) {
    int t = blockIdx.x;
    int b = threadIdx.x & 63;
    int sub = threadIdx.x >> 6;
    int tok = tokens[b * T_ + t];
    const float* er = emb + (size_t)tok * E_;
    for (int e = sub; e < E_; e += 4)
        d_XT[t][e][b] = er[e];
}

// ---------------- input projection GEMM (unchanged, passing) ----------------
__global__ void __launch_bounds__(128) k_gemm_in(const float* __restrict__ Wf,
                                                 const float* __restrict__ Wb,
                                                 const float* __restrict__ bif,
                                                 const float* __restrict__ bib) {
    int gt = blockIdx.x, s = blockIdx.y, dir = blockIdx.z;
    int g0 = gt * 48;
    int torig = dir ? s : (T_ - 1 - s);
    const float* W  = dir ? Wb  : Wf;
    const float* bi = dir ? bib : bif;

    __shared__ __align__(16) float sW[64 * 48];
    __shared__ __align__(16) float sA[64 * 64];

    int tid = threadIdx.x;
    int kh = tid >> 6, r = tid & 63, cg = r >> 3, bg = r & 7;
    int b0 = bg << 3, c0 = cg * 6;

    ull acc[6][4];
#pragma unroll
    for (int j = 0; j < 6; j++) {
        ull init = kh ? 0ull : pk2(bi[g0 + c0 + j]);
#pragma unroll
        for (int p = 0; p < 4; p++) acc[j][p] = init;
    }

    for (int kc = 0; kc < E_ / 64; kc++) {
        __syncthreads();
        for (int idx = tid; idx < 64 * 48; idx += 128) {
            int kk = idx / 48, c = idx - kk * 48;
            sW[idx] = W[(size_t)(kc * 64 + kk) * G_ + g0 + c];
        }
        const float4* src = (const float4*)(&d_XT[torig][kc * 64][0]);
        float4* dst = (float4*)sA;
#pragma unroll
        for (int i = 0; i < 8; i++) dst[tid + i * 128] = src[tid + i * 128];
        __syncthreads();

        const float* hb  = sA + (kh * 32) * 64;
        const float* wb_ = sW + (kh * 32) * 48;
#pragma unroll 4
        for (int kk = 0; kk < 32; kk++) {
            ull hp[4];
#pragma unroll
            for (int p = 0; p < 4; p++) hp[p] = *(const ull*)(hb + kk * 64 + b0 + 2 * p);
#pragma unroll
            for (int j = 0; j < 6; j++) {
                ull us = pk2(wb_[kk * 48 + c0 + j]);
#pragma unroll
                for (int p = 0; p < 4; p++) fma2(acc[j][p], hp[p], us);
            }
        }
    }
    __syncthreads();
    ull* part = (ull*)sA;
    if (kh) {
#pragma unroll
        for (int j = 0; j < 6; j++)
#pragma unroll
            for (int p = 0; p < 4; p++) part[r * 24 + j * 4 + p] = acc[j][p];
    }
    __syncthreads();
    if (!kh) {
#pragma unroll
        for (int j = 0; j < 6; j++) {
#pragma unroll
            for (int q = 0; q < 2; q++) {
                F4 o;
                o.u[0] = add2(acc[j][2 * q + 0], part[r * 24 + j * 4 + 2 * q + 0]);
                o.u[1] = add2(acc[j][2 * q + 1], part[r * 24 + j * 4 + 2 * q + 1]);
                *(float4*)(&d_xg[dir][s][g0 + c0 + j][b0 + 4 * q]) = o.v;
            }
        }
    }
}

// ---------------- persistent recurrent kernel ----------------
// R15: 256 threads (255-reg headroom), 4-way k-split, per-thread tile 6c x 8b.
// Each weight reused across 8 b -> warp-LDS per SM halves vs R11. h arrives as
// 2 natural-pair LDG.128 per k-row (b-pairs are the f32x2 lanes; zero h MOVs).
// Weight dup via pk2 on the idle alu pipe. 4-row-deep h pipeline covers L2 lat.
__global__ void __launch_bounds__(256, 1) k_rec(const float* __restrict__ Uf,
                                                const float* __restrict__ Ub,
                                                const float* __restrict__ bhf,
                                                const float* __restrict__ bhb) {
    extern __shared__ __align__(16) float smem[];
    float* sU = smem;                // U_*48 floats = 196608 B, layout [k][48]
    float* sS = smem + U_ * 48;      // 8192 floats scratch

    int dir = blockIdx.x >> 6;
    int uc  = blockIdx.x & 63;
    int u0  = uc << 4;
    const float* Uw = dir ? Ub : Uf;
    const float* bh = dir ? bhb : bhf;
    int tid = threadIdx.x;
    unsigned nCTA = gridDim.x;

    // one-time: this CTA's Uw slice [1024 x 48] -> smem. col c: gate c>>4, u = u0+(c&15)
    for (int idx = tid; idx < U_ * 48; idx += 256) {
        int k = idx / 48, c = idx - k * 48;
        sU[idx] = Uw[(size_t)k * G_ + (c >> 4) * U_ + u0 + (c & 15)];
    }

    int kh = tid >> 6;                 // 0..3: contiguous k quarter [kh*256,(kh+1)*256)
    int r  = tid & 63;
    int cg = r & 7, bg = r >> 3;       // 8 col-groups x 8 b-groups
    int c0 = cg * 6, b0 = bg * 8;

    // bias (kh0 only): full bias in both lanes (lanes are b-pairs)
    ull binit[6];
#pragma unroll
    for (int j = 0; j < 6; j++) {
        if (kh) { binit[j] = 0ull; continue; }
        int c = c0 + j;
        binit[j] = pk2(bh[(c >> 4) * U_ + u0 + (c & 15)]);
    }

    // epilogue mapping: one (u, 4b) float4 task per thread
    int eu = tid >> 4;                 // 0..15
    int eb = (tid & 15) * 4;           // 0..60
    int gu = u0 + eu;
    const float* xgbase = &d_xg[dir][0][0][0];
    const float* ubB = sU + (size_t)(kh * 256) * 48 + c0;

    __syncthreads();                   // sU resident

    for (int s = 0; s < T_; s++) {
        const float* hprev = (s == 0) ? &d_h0[0][0] : &d_outs[dir][s - 1][0][0];
        const float* hb = hprev + (size_t)(kh * 256) * 64 + b0;

        // prefetch epilogue operands (consumed after the mainloop)
        const float* xs = xgbase + (size_t)s * G_ * B_;
        F4 xz, xr, xh, hpv;
        xz.v  = *(const float4*)(xs + (size_t)gu * B_ + eb);
        xr.v  = *(const float4*)(xs + (size_t)(U_ + gu) * B_ + eb);
        xh.v  = *(const float4*)(xs + (size_t)(2 * U_ + gu) * B_ + eb);
        hpv.v = __ldcg((const float4*)(hprev + (size_t)gu * B_ + eb));

        ull acc[6][4];
#pragma unroll
        for (int j = 0; j < 6; j++)
#pragma unroll
            for (int b = 0; b < 4; b++) acc[j][b] = binit[j];

        // ---- 4-deep pipelined mainloop: 256 k rows, zero interior barriers ----
#define LOADR(A, Bv, g) do {                                              \
            (A).v  = __ldcg((const float4*)(hb + (size_t)(g) * 64));      \
            (Bv).v = __ldcg((const float4*)(hb + (size_t)(g) * 64 + 4)); } while (0)
#define COMPR(A, Bv, g) do {                                              \
            const float* wp = ubB + (size_t)(g) * 48;                     \
            F2 w01, w23, w45;                                             \
            w01.v = *(const float2*)(wp);                                 \
            w23.v = *(const float2*)(wp + 2);                             \
            w45.v = *(const float2*)(wp + 4);                             \
            ull hp0 = (A).u[0], hp1 = (A).u[1];                           \
            ull hp2 = (Bv).u[0], hp3 = (Bv).u[1];                         \
            ull w;                                                        \
            w = pk2(w01.f[0]);                                            \
            fma2(acc[0][0], hp0, w); fma2(acc[0][1], hp1, w);             \
            fma2(acc[0][2], hp2, w); fma2(acc[0][3], hp3, w);             \
            w = pk2(w01.f[1]);                                            \
            fma2(acc[1][0], hp0, w); fma2(acc[1][1], hp1, w);             \
            fma2(acc[1][2], hp2, w); fma2(acc[1][3], hp3, w);             \
            w = pk2(w23.f[0]);                                            \
            fma2(acc[2][0], hp0, w); fma2(acc[2][1], hp1, w);             \
            fma2(acc[2][2], hp2, w); fma2(acc[2][3], hp3, w);             \
            w = pk2(w23.f[1]);                                            \
            fma2(acc[3][0], hp0, w); fma2(acc[3][1], hp1, w);             \
            fma2(acc[3][2], hp2, w); fma2(acc[3][3], hp3, w);             \
            w = pk2(w45.f[0]);                                            \
            fma2(acc[4][0], hp0, w); fma2(acc[4][1], hp1, w);             \
            fma2(acc[4][2], hp2, w); fma2(acc[4][3], hp3, w);             \
            w = pk2(w45.f[1]);                                            \
            fma2(acc[5][0], hp0, w); fma2(acc[5][1], hp1, w);             \
            fma2(acc[5][2], hp2, w); fma2(acc[5][3], hp3, w); } while (0)

        F4 a0, a1, b0v, b1v, c0v, c1v, d0v, d1v;
        LOADR(a0, a1, 0);
        LOADR(b0v, b1v, 1);
        LOADR(c0v, c1v, 2);
        LOADR(d0v, d1v, 3);
#pragma unroll 1
        for (int it = 0; it < 63; it++) {
            int g = 4 * it;
            COMPR(a0, a1, g);     LOADR(a0, a1, g + 4);
            COMPR(b0v, b1v, g + 1); LOADR(b0v, b1v, g + 5);
            COMPR(c0v, c1v, g + 2); LOADR(c0v, c1v, g + 6);
            COMPR(d0v, d1v, g + 3); LOADR(d0v, d1v, g + 7);
        }
        COMPR(a0, a1, 252);
        COMPR(b0v, b1v, 253);
        COMPR(c0v, c1v, 254);
        COMPR(d0v, d1v, 255);
#undef LOADR
#undef COMPR

        // cross-kh reduce. P0 = ull[0,1536) (floats [0,3072)); P1 = ull[1536,3072)
        // (floats [3072,6144)). sG = float[4096,7360): overlaps P1 only after its
        // last read (sync B) and is written after sync C.
        ull* part = (ull*)sS;
        if (kh == 2) {
#pragma unroll
            for (int j = 0; j < 6; j++)
#pragma unroll
                for (int b = 0; b < 4; b++) part[r * 24 + j * 4 + b] = acc[j][b];
        }
        if (kh == 3) {
#pragma unroll
            for (int j = 0; j < 6; j++)
#pragma unroll
                for (int b = 0; b < 4; b++) part[1536 + r * 24 + j * 4 + b] = acc[j][b];
        }
        __syncthreads();   // sync A
        if (kh == 0) {
#pragma unroll
            for (int j = 0; j < 6; j++)
#pragma unroll
                for (int b = 0; b < 4; b++) acc[j][b] = add2(acc[j][b], part[r * 24 + j * 4 + b]);
        }
        if (kh == 1) {
#pragma unroll
            for (int j = 0; j < 6; j++)
#pragma unroll
                for (int b = 0; b < 4; b++) acc[j][b] = add2(acc[j][b], part[1536 + r * 24 + j * 4 + b]);
        }
        __syncthreads();   // sync B (P1 dead after this)
        if (kh == 1) {
#pragma unroll
            for (int j = 0; j < 6; j++)
#pragma unroll
                for (int b = 0; b < 4; b++) part[r * 24 + j * 4 + b] = acc[j][b];
        }
        __syncthreads();   // sync C
        float* sG = sS + 4096;
        if (kh == 0) {
#pragma unroll
            for (int j = 0; j < 6; j++) {
#pragma unroll
                for (int b = 0; b < 4; b++) {
                    ull v = add2(acc[j][b], part[r * 24 + j * 4 + b]);
                    float lo, hi; unpk2(v, lo, hi);
                    sG[(c0 + j) * SGST + b0 + 2 * b] = lo;
                    sG[(c0 + j) * SGST + b0 + 2 * b + 1] = hi;
                }
            }
        }
        __syncthreads();   // sync D

        // epilogue: gates -> h_new, one (u, 4b) per thread; store to d_outs[s]
        {
            F4 hz, hr, hh, hn;
            hz.v = *(float4*)(sG + eu * SGST + eb);
            hr.v = *(float4*)(sG + (16 + eu) * SGST + eb);
            hh.v = *(float4*)(sG + (32 + eu) * SGST + eb);
#pragma unroll
            for (int e = 0; e < 4; e++) {
                float z  = sigf(xz.f[e] + hz.f[e]);
                float rr = sigf(xr.f[e] + hr.f[e]);
                float hc = tanhf(xh.f[e] + rr * hh.f[e]);
                hn.f[e]  = z * hpv.f[e] + (1.0f - z) * hc;
            }
            __stcg((float4*)(&d_outs[dir][s][gu][eb]), hn.v);
        }

        // grid barrier (monotonic; 128 co-resident CTAs)
        __syncthreads();
        if (tid == 0) {
            __threadfence();
            unsigned target = nCTA * (unsigned)(s + 1);
            unsigned v = atomicAdd(&g_bar, 1u) + 1u;
            while (v < target) {
                __nanosleep(128);
                v = atomicAdd(&g_bar, 0u);
            }
            __threadfence();
        }
        __syncthreads();
    }
}

// ---------------- combine: out[b][t][u] = outs_f[t][u][b] + outs_b[T-1-t][u][b] ----------------
__global__ void k_comb(float* __restrict__ out) {
    __shared__ float sT[32][33];
    int t = blockIdx.x, u0 = blockIdx.y * 32, b0 = blockIdx.z * 32;
    int tx = threadIdx.x, ty = threadIdx.y;
#pragma unroll
    for (int i = 0; i < 4; i++) {
        int u = ty + i * 8;
        sT[u][tx] = d_outs[0][t][u0 + u][b0 + tx] + d_outs[1][T_ - 1 - t][u0 + u][b0 + tx];
    }
    __syncthreads();
#pragma unroll
    for (int i = 0; i < 4; i++) {
        int b = ty + i * 8;
        out[((size_t)(b0 + b) * T_ + t) * U_ + u0 + tx] = sT[tx][b];
    }
}

// ---------------- hidden concat ----------------
__global__ void k_hid(float* __restrict__ out) {
    __shared__ float sT[32][33];
    int u0 = blockIdx.x * 32, dir = blockIdx.y, b0 = blockIdx.z * 32;
    int tx = threadIdx.x, ty = threadIdx.y;
#pragma unroll
    for (int i = 0; i < 4; i++) {
        int u = ty + i * 8;
        sT[u][tx] = d_outs[dir][T_ - 1][u0 + u][b0 + tx];
    }
    __syncthreads();
#pragma unroll
    for (int i = 0; i < 4; i++) {
        int b = ty + i * 8;
        out[HID_OFF + (size_t)(b0 + b) * (2 * U_) + dir * U_ + u0 + tx] = sT[tx][b];
    }
}

extern "C" void kernel_launch(void* const* d_in, const int* in_sizes, int n_in,
                              void* d_out, int out_size) {
    const int*   tokens = (const int*)d_in[0];
    const float* emb    = (const float*)d_in[1];
    const float* Wf     = (const float*)d_in[2];
    const float* Uf     = (const float*)d_in[3];
    const float* bif    = (const float*)d_in[4];
    const float* bhf    = (const float*)d_in[5];
    const float* Wb     = (const float*)d_in[6];
    const float* Ub     = (const float*)d_in[7];
    const float* bib    = (const float*)d_in[8];
    const float* bhb    = (const float*)d_in[9];
    float* out = (float*)d_out;

    const int SMEM_REC = (U_ * 48 + 8192) * (int)sizeof(float);  // 229376 B
    cudaFuncSetAttribute(k_rec, cudaFuncAttributeMaxDynamicSharedMemorySize, SMEM_REC);

    k_init<<<64, 256>>>();
    k_embed<<<T_, 256>>>(tokens, emb);
    {
        dim3 g(64, T_, 2);
        k_gemm_in<<<g, 128>>>(Wf, Wb, bif, bib);
    }
    k_rec<<<128, 256, SMEM_REC>>>(Uf, Ub, bhf, bhb);
    {
        dim3 g(T_, U_ / 32, B_ / 32);
        k_comb<<<g, dim3(32, 8)>>>(out);
    }
    {
        dim3 g(U_ / 32, 2, B_ / 32);
        k_hid<<<g, dim3(32, 8)>>>(out);
    }
    (void)in_sizes; (void)n_in; (void)out_size;
}

// round 16
// speedup vs baseline: 1.3069x; 1.1227x over previous
#include <cuda_runtime.h>
#include <cstdint>

#define B_ 64
#define T_ 128
#define E_ 512
#define U_ 1024
#define G_ 3072          // 3*U
#define SGST 68          // sG row stride (floats)
#define HID_OFF (B_*T_*U_)

typedef unsigned long long ull;

// ---------------- device scratch (static, allocation-free) ----------------
__device__ __align__(256) float d_XT[T_][E_][B_];       // emb(tokens), [t_orig][e][b]
__device__ __align__(256) float d_xg[2][T_][G_][B_];    // input projections per scan step
__device__ __align__(256) float d_outs[2][T_][U_][B_];  // per-dir hidden sequences (= h chain)
__device__ __align__(256) float d_h0[U_][B_];           // zero initial state (both dirs)
__device__ unsigned g_bar;                              // monotonic grid barrier

// ---------------- f32x2 helpers (Blackwell packed fp32) ----------------
__device__ __forceinline__ ull pk2(float v) {
    ull r; asm("mov.b64 %0, {%1, %1};" : "=l"(r) : "f"(v)); return r;
}
__device__ __forceinline__ void unpk2(ull v, float& lo, float& hi) {
    asm("mov.b64 {%0, %1}, %2;" : "=f"(lo), "=f"(hi) : "l"(v));
}
__device__ __forceinline__ void fma2(ull& d, ull a, ull b) {
    asm("fma.rn.f32x2 %0, %1, %2, %0;" : "+l"(d) : "l"(a), "l"(b));
}
__device__ __forceinline__ ull add2(ull a, ull b) {
    ull r; asm("add.rn.f32x2 %0, %1, %2;" : "=l"(r) : "l"(a), "l"(b)); return r;
}
__device__ __forceinline__ float sigf(float x) { return 1.0f / (1.0f + __expf(-x)); }

union F4 { float4 v; float f[4]; ull u[2]; };
union F2 { float2 v; float f[2]; };

// ---------------- init: zero h0, reset barrier ----------------
__global__ void k_init() {
    int n = U_ * B_;
    float* p = &d_h0[0][0];
    for (int i = blockIdx.x * blockDim.x + threadIdx.x; i < n; i += gridDim.x * blockDim.x)
        p[i] = 0.0f;
    if (blockIdx.x == 0 && threadIdx.x == 0) g_bar = 0u;
}

// ---------------- embedding gather (transposed store) ----------------
__global__ void k_embed(const int* __restrict__ tokens, const float* __restrict__ emb) {
    int t = blockIdx.x;
    int b = threadIdx.x & 63;
    int sub = threadIdx.x >> 6;
    int tok = tokens[b * T_ + t];
    const float* er = emb + (size_t)tok * E_;
    for (int e = sub; e < E_; e += 4)
        d_XT[t][e][b] = er[e];
}

// ---------------- input projection GEMM (unchanged, passing) ----------------
__global__ void __launch_bounds__(128) k_gemm_in(const float* __restrict__ Wf,
                                                 const float* __restrict__ Wb,
                                                 const float* __restrict__ bif,
                                                 const float* __restrict__ bib) {
    int gt = blockIdx.x, s = blockIdx.y, dir = blockIdx.z;
    int g0 = gt * 48;
    int torig = dir ? s : (T_ - 1 - s);
    const float* W  = dir ? Wb  : Wf;
    const float* bi = dir ? bib : bif;

    __shared__ __align__(16) float sW[64 * 48];
    __shared__ __align__(16) float sA[64 * 64];

    int tid = threadIdx.x;
    int kh = tid >> 6, r = tid & 63, cg = r >> 3, bg = r & 7;
    int b0 = bg << 3, c0 = cg * 6;

    ull acc[6][4];
#pragma unroll
    for (int j = 0; j < 6; j++) {
        ull init = kh ? 0ull : pk2(bi[g0 + c0 + j]);
#pragma unroll
        for (int p = 0; p < 4; p++) acc[j][p] = init;
    }

    for (int kc = 0; kc < E_ / 64; kc++) {
        __syncthreads();
        for (int idx = tid; idx < 64 * 48; idx += 128) {
            int kk = idx / 48, c = idx - kk * 48;
            sW[idx] = W[(size_t)(kc * 64 + kk) * G_ + g0 + c];
        }
        const float4* src = (const float4*)(&d_XT[torig][kc * 64][0]);
        float4* dst = (float4*)sA;
#pragma unroll
        for (int i = 0; i < 8; i++) dst[tid + i * 128] = src[tid + i * 128];
        __syncthreads();

        const float* hb  = sA + (kh * 32) * 64;
        const float* wb_ = sW + (kh * 32) * 48;
#pragma unroll 4
        for (int kk = 0; kk < 32; kk++) {
            ull hp[4];
#pragma unroll
            for (int p = 0; p < 4; p++) hp[p] = *(const ull*)(hb + kk * 64 + b0 + 2 * p);
#pragma unroll
            for (int j = 0; j < 6; j++) {
                ull us = pk2(wb_[kk * 48 + c0 + j]);
#pragma unroll
                for (int p = 0; p < 4; p++) fma2(acc[j][p], hp[p], us);
            }
        }
    }
    __syncthreads();
    ull* part = (ull*)sA;
    if (kh) {
#pragma unroll
        for (int j = 0; j < 6; j++)
#pragma unroll
            for (int p = 0; p < 4; p++) part[r * 24 + j * 4 + p] = acc[j][p];
    }
    __syncthreads();
    if (!kh) {
#pragma unroll
        for (int j = 0; j < 6; j++) {
#pragma unroll
            for (int q = 0; q < 2; q++) {
                F4 o;
                o.u[0] = add2(acc[j][2 * q + 0], part[r * 24 + j * 4 + 2 * q + 0]);
                o.u[1] = add2(acc[j][2 * q + 1], part[r * 24 + j * 4 + 2 * q + 1]);
                *(float4*)(&d_xg[dir][s][g0 + c0 + j][b0 + 4 * q]) = o.v;
            }
        }
    }
}

// ---------------- persistent recurrent kernel ----------------
// R16: 512 threads, 8-way k-split (128 rows each), per-thread tile 6c x 8b
// with b-pair f32x2 accumulators. 3 LDS.64 + 2 LDG.128 per k-row per thread
// (halved LDS of R11 at full 4-warps/SMSP occupancy). Depth-2 h pipeline.
// 8-slice smem reduce tree; epilogue operand loads overlap the reduce.
__global__ void __launch_bounds__(512, 1) k_rec(const float* __restrict__ Uf,
                                                const float* __restrict__ Ub,
                                                const float* __restrict__ bhf,
                                                const float* __restrict__ bhb) {
    extern __shared__ __align__(16) float smem[];
    float* sU = smem;                // U_*48 floats = 196608 B, layout [k][48]
    float* sS = smem + U_ * 48;      // 8192 floats scratch

    int dir = blockIdx.x >> 6;
    int uc  = blockIdx.x & 63;
    int u0  = uc << 4;
    const float* Uw = dir ? Ub : Uf;
    const float* bh = dir ? bhb : bhf;
    int tid = threadIdx.x;
    unsigned nCTA = gridDim.x;

    // one-time: this CTA's Uw slice [1024 x 48] -> smem. col c: gate c>>4, u = u0+(c&15)
    for (int idx = tid; idx < U_ * 48; idx += 512) {
        int k = idx / 48, c = idx - k * 48;
        sU[idx] = Uw[(size_t)k * G_ + (c >> 4) * U_ + u0 + (c & 15)];
    }

    int kh = tid >> 6;                 // 0..7: k slice [kh*128,(kh+1)*128)
    int r  = tid & 63;
    int cg = r & 7, bg = r >> 3;       // 8 col-groups x 8 b-groups
    int c0 = cg * 6, b0 = bg * 8;

    // bias (kh0 only): full bias in both lanes (lanes are b-pairs)
    ull binit[6];
#pragma unroll
    for (int j = 0; j < 6; j++) {
        if (kh) { binit[j] = 0ull; continue; }
        int c = c0 + j;
        binit[j] = pk2(bh[(c >> 4) * U_ + u0 + (c & 15)]);
    }

    // epilogue mapping: one (u, 2b) float2 task per thread (coalesced per warp)
    int eu = tid >> 5;                 // 0..15
    int eb = (tid & 31) * 2;           // 0..62
    int gu = u0 + eu;
    const float* xgbase = &d_xg[dir][0][0][0];
    const float* ubB = sU + (size_t)(kh * 128) * 48 + c0;

    __syncthreads();                   // sU resident

    for (int s = 0; s < T_; s++) {
        const float* hprev = (s == 0) ? &d_h0[0][0] : &d_outs[dir][s - 1][0][0];
        const float* hb = hprev + (size_t)(kh * 128) * 64 + b0;

        ull acc[6][4];
#pragma unroll
        for (int j = 0; j < 6; j++)
#pragma unroll
            for (int b = 0; b < 4; b++) acc[j][b] = binit[j];

        // ---- depth-2 pipelined mainloop: 128 k rows, zero interior barriers ----
#define LOADR(A, Bv, g) do {                                              \
            (A).v  = __ldcg((const float4*)(hb + (size_t)(g) * 64));      \
            (Bv).v = __ldcg((const float4*)(hb + (size_t)(g) * 64 + 4)); } while (0)
#define COMPR(A, Bv, g) do {                                              \
            const float* wp = ubB + (size_t)(g) * 48;                     \
            F2 w01, w23, w45;                                             \
            w01.v = *(const float2*)(wp);                                 \
            w23.v = *(const float2*)(wp + 2);                             \
            w45.v = *(const float2*)(wp + 4);                             \
            ull hp0 = (A).u[0], hp1 = (A).u[1];                           \
            ull hp2 = (Bv).u[0], hp3 = (Bv).u[1];                         \
            ull w;                                                        \
            w = pk2(w01.f[0]);                                            \
            fma2(acc[0][0], hp0, w); fma2(acc[0][1], hp1, w);             \
            fma2(acc[0][2], hp2, w); fma2(acc[0][3], hp3, w);             \
            w = pk2(w01.f[1]);                                            \
            fma2(acc[1][0], hp0, w); fma2(acc[1][1], hp1, w);             \
            fma2(acc[1][2], hp2, w); fma2(acc[1][3], hp3, w);             \
            w = pk2(w23.f[0]);                                            \
            fma2(acc[2][0], hp0, w); fma2(acc[2][1], hp1, w);             \
            fma2(acc[2][2], hp2, w); fma2(acc[2][3], hp3, w);             \
            w = pk2(w23.f[1]);                                            \
            fma2(acc[3][0], hp0, w); fma2(acc[3][1], hp1, w);             \
            fma2(acc[3][2], hp2, w); fma2(acc[3][3], hp3, w);             \
            w = pk2(w45.f[0]);                                            \
            fma2(acc[4][0], hp0, w); fma2(acc[4][1], hp1, w);             \
            fma2(acc[4][2], hp2, w); fma2(acc[4][3], hp3, w);             \
            w = pk2(w45.f[1]);                                            \
            fma2(acc[5][0], hp0, w); fma2(acc[5][1], hp1, w);             \
            fma2(acc[5][2], hp2, w); fma2(acc[5][3], hp3, w); } while (0)

        F4 a0, a1, b0v, b1v;
        LOADR(a0, a1, 0);
        LOADR(b0v, b1v, 1);
#pragma unroll 1
        for (int it = 0; it < 63; it++) {
            int g = 2 * it;
            COMPR(a0, a1, g);       LOADR(a0, a1, g + 2);
            COMPR(b0v, b1v, g + 1); LOADR(b0v, b1v, g + 3);
        }
        COMPR(a0, a1, 126);
        COMPR(b0v, b1v, 127);
#undef LOADR
#undef COMPR

        // epilogue operand loads issued now: DRAM latency hides under reduce tree
        const float* xs = xgbase + (size_t)s * G_ * B_;
        F2 xz, xr, xh, hpv;
        xz.v  = *(const float2*)(xs + (size_t)gu * B_ + eb);
        xr.v  = *(const float2*)(xs + (size_t)(U_ + gu) * B_ + eb);
        xh.v  = *(const float2*)(xs + (size_t)(2 * U_ + gu) * B_ + eb);
        hpv.v = __ldcg((const float2*)(hprev + (size_t)gu * B_ + eb));

        // ---- 8-slice reduce tree. P0 = ull sS[0,1536) (floats [0,3072));
        //      P1 = ull[1536,3072) (floats [3072,6144)); sG = float[3072,6336)
        //      (overlays P1 only after its final read).
        ull* part = (ull*)sS;
        float* sG = sS + 3072;
        // R1: kh1->P0, kh3->P1 ; kh0+=P0, kh2+=P1
        if (kh == 1 || kh == 3) {
            ull* dst = part + ((kh == 1) ? 0 : 1536);
#pragma unroll
            for (int j = 0; j < 6; j++)
#pragma unroll
                for (int b = 0; b < 4; b++) dst[r * 24 + j * 4 + b] = acc[j][b];
        }
        __syncthreads();
        if (kh == 0 || kh == 2) {
            ull* src = part + ((kh == 0) ? 0 : 1536);
#pragma unroll
            for (int j = 0; j < 6; j++)
#pragma unroll
                for (int b = 0; b < 4; b++) acc[j][b] = add2(acc[j][b], src[r * 24 + j * 4 + b]);
        }
        __syncthreads();
        // R2: kh5->P0, kh7->P1 ; kh4+=P0, kh6+=P1
        if (kh == 5 || kh == 7) {
            ull* dst = part + ((kh == 5) ? 0 : 1536);
#pragma unroll
            for (int j = 0; j < 6; j++)
#pragma unroll
                for (int b = 0; b < 4; b++) dst[r * 24 + j * 4 + b] = acc[j][b];
        }
        __syncthreads();
        if (kh == 4 || kh == 6) {
            ull* src = part + ((kh == 4) ? 0 : 1536);
#pragma unroll
            for (int j = 0; j < 6; j++)
#pragma unroll
                for (int b = 0; b < 4; b++) acc[j][b] = add2(acc[j][b], src[r * 24 + j * 4 + b]);
        }
        __syncthreads();
        // R3: kh2->P0, kh6->P1 ; kh0+=P0, kh4+=P1   (last read of P1)
        if (kh == 2 || kh == 6) {
            ull* dst = part + ((kh == 2) ? 0 : 1536);
#pragma unroll
            for (int j = 0; j < 6; j++)
#pragma unroll
                for (int b = 0; b < 4; b++) dst[r * 24 + j * 4 + b] = acc[j][b];
        }
        __syncthreads();
        if (kh == 0 || kh == 4) {
            ull* src = part + ((kh == 0) ? 0 : 1536);
#pragma unroll
            for (int j = 0; j < 6; j++)
#pragma unroll
                for (int b = 0; b < 4; b++) acc[j][b] = add2(acc[j][b], src[r * 24 + j * 4 + b]);
        }
        __syncthreads();
        // R4: kh4->P0 ; kh0 final -> sG (sG overlays dead P1)
        if (kh == 4) {
#pragma unroll
            for (int j = 0; j < 6; j++)
#pragma unroll
                for (int b = 0; b < 4; b++) part[r * 24 + j * 4 + b] = acc[j][b];
        }
        __syncthreads();
        if (kh == 0) {
#pragma unroll
            for (int j = 0; j < 6; j++) {
#pragma unroll
                for (int b = 0; b < 4; b++) {
                    ull v = add2(acc[j][b], part[r * 24 + j * 4 + b]);
                    float lo, hi; unpk2(v, lo, hi);
                    sG[(c0 + j) * SGST + b0 + 2 * b] = lo;
                    sG[(c0 + j) * SGST + b0 + 2 * b + 1] = hi;
                }
            }
        }
        __syncthreads();

        // epilogue: gates -> h_new, one (u, 2b) per thread; store to d_outs[s]
        {
            F2 hz, hr, hh, hn;
            hz.v = *(float2*)(sG + eu * SGST + eb);
            hr.v = *(float2*)(sG + (16 + eu) * SGST + eb);
            hh.v = *(float2*)(sG + (32 + eu) * SGST + eb);
#pragma unroll
            for (int e = 0; e < 2; e++) {
                float z  = sigf(xz.f[e] + hz.f[e]);
                float rr = sigf(xr.f[e] + hr.f[e]);
                float hc = tanhf(xh.f[e] + rr * hh.f[e]);
                hn.f[e]  = z * hpv.f[e] + (1.0f - z) * hc;
            }
            __stcg((float2*)(&d_outs[dir][s][gu][eb]), hn.v);
        }

        // grid barrier (monotonic; 128 co-resident CTAs)
        __syncthreads();
        if (tid == 0) {
            __threadfence();
            unsigned target = nCTA * (unsigned)(s + 1);
            unsigned v = atomicAdd(&g_bar, 1u) + 1u;
            while (v < target) {
                __nanosleep(128);
                v = atomicAdd(&g_bar, 0u);
            }
            __threadfence();
        }
        __syncthreads();
    }
}

// ---------------- combine: out[b][t][u] = outs_f[t][u][b] + outs_b[T-1-t][u][b] ----------------
__global__ void k_comb(float* __restrict__ out) {
    __shared__ float sT[32][33];
    int t = blockIdx.x, u0 = blockIdx.y * 32, b0 = blockIdx.z * 32;
    int tx = threadIdx.x, ty = threadIdx.y;
#pragma unroll
    for (int i = 0; i < 4; i++) {
        int u = ty + i * 8;
        sT[u][tx] = d_outs[0][t][u0 + u][b0 + tx] + d_outs[1][T_ - 1 - t][u0 + u][b0 + tx];
    }
    __syncthreads();
#pragma unroll
    for (int i = 0; i < 4; i++) {
        int b = ty + i * 8;
        out[((size_t)(b0 + b) * T_ + t) * U_ + u0 + tx] = sT[tx][b];
    }
}

// ---------------- hidden concat ----------------
__global__ void k_hid(float* __restrict__ out) {
    __shared__ float sT[32][33];
    int u0 = blockIdx.x * 32, dir = blockIdx.y, b0 = blockIdx.z * 32;
    int tx = threadIdx.x, ty = threadIdx.y;
#pragma unroll
    for (int i = 0; i < 4; i++) {
        int u = ty + i * 8;
        sT[u][tx] = d_outs[dir][T_ - 1][u0 + u][b0 + tx];
    }
    __syncthreads();
#pragma unroll
    for (int i = 0; i < 4; i++) {
        int b = ty + i * 8;
        out[HID_OFF + (size_t)(b0 + b) * (2 * U_) + dir * U_ + u0 + tx] = sT[tx][b];
    }
}

extern "C" void kernel_launch(void* const* d_in, const int* in_sizes, int n_in,
                              void* d_out, int out_size) {
    const int*   tokens = (const int*)d_in[0];
    const float* emb    = (const float*)d_in[1];
    const float* Wf     = (const float*)d_in[2];
    const float* Uf     = (const float*)d_in[3];
    const float* bif    = (const float*)d_in[4];
    const float* bhf    = (const float*)d_in[5];
    const float* Wb     = (const float*)d_in[6];
    const float* Ub     = (const float*)d_in[7];
    const float* bib    = (const float*)d_in[8];
    const float* bhb    = (const float*)d_in[9];
    float* out = (float*)d_out;

    const int SMEM_REC = (U_ * 48 + 8192) * (int)sizeof(float);  // 229376 B
    cudaFuncSetAttribute(k_rec, cudaFuncAttributeMaxDynamicSharedMemorySize, SMEM_REC);

    k_init<<<64, 256>>>();
    k_embed<<<T_, 256>>>(tokens, emb);
    {
        dim3 g(64, T_, 2);
        k_gemm_in<<<g, 128>>>(Wf, Wb, bif, bib);
    }
    k_rec<<<128, 512, SMEM_REC>>>(Uf, Ub, bhf, bhb);
    {
        dim3 g(T_, U_ / 32, B_ / 32);
        k_comb<<<g, dim3(32, 8)>>>(out);
    }
    {
        dim3 g(U_ / 32, 2, B_ / 32);
        k_hid<<<g, dim3(32, 8)>>>(out);
    }
    (void)in_sizes; (void)n_in; (void)out_size;
}

// round 17
// speedup vs baseline: 2.1969x; 1.6810x over previous
#include <cuda_runtime.h>
#include <cuda_bf16.h>
#include <cstdint>

#define B_ 64
#define T_ 128
#define E_ 512
#define U_ 1024
#define G_ 3072          // 3*U
#define SGST 68          // sG row stride (floats)
#define HID_OFF (B_*T_*U_)

typedef unsigned long long ull;

// ---------------- device scratch (static, allocation-free) ----------------
__device__ __align__(256) float d_XT[T_][E_][B_];       // emb(tokens), [t_orig][e][b]
__device__ __align__(256) float d_xg[2][T_][G_][B_];    // input projections per scan step
__device__ __align__(256) float d_outs[2][T_][U_][B_];  // per-dir hidden fp32 [u][b]
__device__ __align__(256) float d_h0[U_][B_];           // zero initial state
// h in B-fragment-packed bf16-split form: [dir][pp][hl(hi/lo)][kt(64)][512 words]
// word w: b = w>>3, q = (w>>1)&3, half = w&1 -> kp = kt*8 + q + 4*half,
// word = bf16x2( h[2kp][b], h[2kp+1][b] )
__device__ __align__(256) unsigned int d_hsp[2][2][2][64][512];
__device__ unsigned g_bar;                              // monotonic grid barrier

// ---------------- f32x2 helpers (kept for k_gemm_in) ----------------
__device__ __forceinline__ ull pk2(float v) {
    ull r; asm("mov.b64 %0, {%1, %1};" : "=l"(r) : "f"(v)); return r;
}
__device__ __forceinline__ void fma2(ull& d, ull a, ull b) {
    asm("fma.rn.f32x2 %0, %1, %2, %0;" : "+l"(d) : "l"(a), "l"(b));
}
__device__ __forceinline__ ull add2(ull a, ull b) {
    ull r; asm("add.rn.f32x2 %0, %1, %2;" : "=l"(r) : "l"(a), "l"(b)); return r;
}
__device__ __forceinline__ float sigf(float x) { return 1.0f / (1.0f + __expf(-x)); }

union F4 { float4 v; float f[4]; ull u[2]; };

// bf16 mma m16n8k16, row.col, f32 accum
__device__ __forceinline__ void mma_bf16(float& d0, float& d1, float& d2, float& d3,
                                         uint32_t a0, uint32_t a1, uint32_t a2, uint32_t a3,
                                         uint32_t b0, uint32_t b1) {
    asm("mma.sync.aligned.m16n8k16.row.col.f32.bf16.bf16.f32 "
        "{%0,%1,%2,%3},{%4,%5,%6,%7},{%8,%9},{%0,%1,%2,%3};"
        : "+f"(d0), "+f"(d1), "+f"(d2), "+f"(d3)
        : "r"(a0), "r"(a1), "r"(a2), "r"(a3), "r"(b0), "r"(b1));
}

// pack two floats into bf16x2 word (lo half = first), sp=0 -> hi part, sp=1 -> lo residual
__device__ __forceinline__ uint32_t pack_split(float x0, float x1, int sp) {
    __nv_bfloat16 h0 = __float2bfloat16(x0);
    __nv_bfloat16 h1 = __float2bfloat16(x1);
    if (sp) {
        h0 = __float2bfloat16(x0 - __bfloat162float(h0));
        h1 = __float2bfloat16(x1 - __bfloat162float(h1));
    }
    return ((uint32_t)__bfloat16_as_ushort(h1) << 16) | (uint32_t)__bfloat16_as_ushort(h0);
}

// ---------------- init: zero h0 + ALL of d_hsp (determinism), reset barrier ----------------
__global__ void k_init() {
    int tid = blockIdx.x * blockDim.x + threadIdx.x;
    int nth = gridDim.x * blockDim.x;
    int n0 = U_ * B_;
    float* p = &d_h0[0][0];
    for (int i = tid; i < n0; i += nth) p[i] = 0.0f;
    unsigned int* q = &d_hsp[0][0][0][0][0];
    int n1 = 2 * 2 * 2 * 64 * 512;
    for (int i = tid; i < n1; i += nth) q[i] = 0u;
    if (tid == 0) g_bar = 0u;
}

// ---------------- embedding gather (transposed store) ----------------
__global__ void k_embed(const int* __restrict__ tokens, const float* __restrict__ emb) {
    int t = blockIdx.x;
    int b = threadIdx.x & 63;
    int sub = threadIdx.x >> 6;
    int tok = tokens[b * T_ + t];
    const float* er = emb + (size_t)tok * E_;
    for (int e = sub; e < E_; e += 4)
        d_XT[t][e][b] = er[e];
}

// ---------------- input projection GEMM (unchanged, passing) ----------------
__global__ void __launch_bounds__(128) k_gemm_in(const float* __restrict__ Wf,
                                                 const float* __restrict__ Wb,
                                                 const float* __restrict__ bif,
                                                 const float* __restrict__ bib) {
    int gt = blockIdx.x, s = blockIdx.y, dir = blockIdx.z;
    int g0 = gt * 48;
    int torig = dir ? s : (T_ - 1 - s);
    const float* W  = dir ? Wb  : Wf;
    const float* bi = dir ? bib : bif;

    __shared__ __align__(16) float sW[64 * 48];
    __shared__ __align__(16) float sA[64 * 64];

    int tid = threadIdx.x;
    int kh = tid >> 6, r = tid & 63, cg = r >> 3, bg = r & 7;
    int b0 = bg << 3, c0 = cg * 6;

    ull acc[6][4];
#pragma unroll
    for (int j = 0; j < 6; j++) {
        ull init = kh ? 0ull : pk2(bi[g0 + c0 + j]);
#pragma unroll
        for (int p = 0; p < 4; p++) acc[j][p] = init;
    }

    for (int kc = 0; kc < E_ / 64; kc++) {
        __syncthreads();
        for (int idx = tid; idx < 64 * 48; idx += 128) {
            int kk = idx / 48, c = idx - kk * 48;
            sW[idx] = W[(size_t)(kc * 64 + kk) * G_ + g0 + c];
        }
        const float4* src = (const float4*)(&d_XT[torig][kc * 64][0]);
        float4* dst = (float4*)sA;
#pragma unroll
        for (int i = 0; i < 8; i++) dst[tid + i * 128] = src[tid + i * 128];
        __syncthreads();

        const float* hb  = sA + (kh * 32) * 64;
        const float* wb_ = sW + (kh * 32) * 48;
#pragma unroll 4
        for (int kk = 0; kk < 32; kk++) {
            ull hp[4];
#pragma unroll
            for (int p = 0; p < 4; p++) hp[p] = *(const ull*)(hb + kk * 64 + b0 + 2 * p);
#pragma unroll
            for (int j = 0; j < 6; j++) {
                ull us = pk2(wb_[kk * 48 + c0 + j]);
#pragma unroll
                for (int p = 0; p < 4; p++) fma2(acc[j][p], hp[p], us);
            }
        }
    }
    __syncthreads();
    ull* part = (ull*)sA;
    if (kh) {
#pragma unroll
        for (int j = 0; j < 6; j++)
#pragma unroll
            for (int p = 0; p < 4; p++) part[r * 24 + j * 4 + p] = acc[j][p];
    }
    __syncthreads();
    if (!kh) {
#pragma unroll
        for (int j = 0; j < 6; j++) {
#pragma unroll
            for (int q = 0; q < 2; q++) {
                F4 o;
                o.u[0] = add2(acc[j][2 * q + 0], part[r * 24 + j * 4 + 2 * q + 0]);
                o.u[1] = add2(acc[j][2 * q + 1], part[r * 24 + j * 4 + 2 * q + 1]);
                *(float4*)(&d_xg[dir][s][g0 + c0 + j][b0 + 4 * q]) = o.v;
            }
        }
    }
}

// ---------------- persistent recurrent kernel: tensor-core mainloop ----------------
// 128 CTAs (2 dirs x 64 u-chunks of 16), 512 threads, 1 CTA/SM.
// mma.sync m16n8k16 bf16 with 2-term split (hi/lo): gates = Uhi*hhi + Uhi*hlo + Ulo*hhi.
// Weights fragment-packed in smem (one LDS.128 per A fragment, conflict-free).
// h fragments read straight from L2 (d_hsp packed words -> one coalesced LDG.64).
// 16 warps = 4 n-groups (16 b each) x 4 k-groups (256 k each). 4-round smem reduce.
__global__ void __launch_bounds__(512, 1) k_rec(const float* __restrict__ Uf,
                                                const float* __restrict__ Ub,
                                                const float* __restrict__ bhf,
                                                const float* __restrict__ bhb) {
    extern __shared__ __align__(16) unsigned int smemw[];
    // sWA: [kt 64][m 3][sp 2][lane 32][4 words] = 49152 words = 196608 B
    unsigned int* sWA = smemw;
    float* sS = (float*)(smemw + 49152);   // 8192 floats scratch

    int dir = blockIdx.x >> 6;
    int uc  = blockIdx.x & 63;
    int u0  = uc << 4;
    const float* Uw = dir ? Ub : Uf;
    const float* bh = dir ? bhb : bhf;
    int tid = threadIdx.x;
    unsigned nCTA = gridDim.x;

    // one-time: build fragment-packed split weights in smem
    for (int idx = tid; idx < 49152; idx += 512) {
        int t1 = idx >> 2;       int ai = idx & 3;
        int lane = t1 & 31;      int t2 = t1 >> 5;
        int sp = t2 & 1;         int t3 = t2 >> 1;
        int m = t3 % 3;          int kt = t3 / 3;
        int r0 = lane >> 2, q = lane & 3;
        int cc = r0 + 8 * (ai & 1);                 // 0..15 within gate tile
        int kp = kt * 8 + q + 4 * (ai >> 1);
        int col = m * U_ + u0 + cc;                 // gate m, unit u0+cc
        float w0 = Uw[(size_t)(2 * kp) * G_ + col];
        float w1 = Uw[(size_t)(2 * kp + 1) * G_ + col];
        sWA[idx] = pack_split(w0, w1, sp);
    }

    int lane = tid & 31;
    int warp = tid >> 5;
    int ng = warp & 3;           // n-group: n-tiles 2ng, 2ng+1 (b = ng*16 .. +15)
    int kg = warp >> 2;          // k-group: kt in [kg*16, kg*16+16)
    int r0 = lane >> 2, qq = lane & 3;

    // epilogue mapping: w = tid -> (b, q, half) -> two u's of this CTA's slice
    int eb   = tid >> 3;
    int eq   = (tid >> 1) & 3;
    int ehalf = tid & 1;
    int kpl  = eq + 4 * ehalf;
    int cc0  = 2 * kpl, cc1 = cc0 + 1;
    int gu0  = u0 + cc0, gu1 = u0 + cc1;
    float bz0 = bh[gu0], br0 = bh[U_ + gu0], bq0 = bh[2 * U_ + gu0];
    float bz1 = bh[gu1], br1 = bh[U_ + gu1], bq1 = bh[2 * U_ + gu1];

    const float* xgbase = &d_xg[dir][0][0][0];

    __syncthreads();                   // sWA resident

    for (int s = 0; s < T_; s++) {
        int pr = (s + 1) & 1;          // read parity ((s-1)&1); s=0 -> 1 (zeroed)
        int pw = s & 1;
        const unsigned int* hHi = &d_hsp[dir][pr][0][0][0];
        const unsigned int* hLo = &d_hsp[dir][pr][1][0][0];
        const float* hprev = (s == 0) ? &d_h0[0][0] : &d_outs[dir][s - 1][0][0];

        float acc[3][2][4];
#pragma unroll
        for (int m = 0; m < 3; m++)
#pragma unroll
            for (int nt = 0; nt < 2; nt++)
#pragma unroll
                for (int ci = 0; ci < 4; ci++) acc[m][nt][ci] = 0.0f;

        // ---- tensor mainloop: 16 k-tiles, depth-1 B prefetch, zero barriers ----
        int kt0 = kg * 16;
        ull Bc[2][2], Bn[2][2];
#pragma unroll
        for (int nt = 0; nt < 2; nt++) {
            int NT = 2 * ng + nt;
            size_t o0 = (size_t)kt0 * 512 + NT * 64 + lane * 2;
            size_t o1 = (size_t)(kt0 + 1) * 512 + NT * 64 + lane * 2;
            Bc[nt][0] = __ldcg((const ull*)(hHi + o0));
            Bc[nt][1] = __ldcg((const ull*)(hLo + o0));
            Bn[nt][0] = __ldcg((const ull*)(hHi + o1));
            Bn[nt][1] = __ldcg((const ull*)(hLo + o1));
        }
#pragma unroll 1
        for (int kt = 0; kt < 16; kt++) {
            int ktg = kt0 + kt;
            // A fragments: 3m x 2sp, one LDS.128 each (conflict-free)
            uint4 A[3][2];
#pragma unroll
            for (int m = 0; m < 3; m++)
#pragma unroll
                for (int sp = 0; sp < 2; sp++)
                    A[m][sp] = *((const uint4*)sWA + (((size_t)ktg * 3 + m) * 2 + sp) * 32 + lane);
#pragma unroll
            for (int m = 0; m < 3; m++)
#pragma unroll
                for (int nt = 0; nt < 2; nt++) {
                    uint32_t bh0 = (uint32_t)Bc[nt][0], bh1 = (uint32_t)(Bc[nt][0] >> 32);
                    uint32_t bl0 = (uint32_t)Bc[nt][1], bl1 = (uint32_t)(Bc[nt][1] >> 32);
                    float* d = acc[m][nt];
                    mma_bf16(d[0], d[1], d[2], d[3], A[m][0].x, A[m][0].y, A[m][0].z, A[m][0].w, bh0, bh1);
                    mma_bf16(d[0], d[1], d[2], d[3], A[m][0].x, A[m][0].y, A[m][0].z, A[m][0].w, bl0, bl1);
                    mma_bf16(d[0], d[1], d[2], d[3], A[m][1].x, A[m][1].y, A[m][1].z, A[m][1].w, bh0, bh1);
                }
            // rotate prefetch
            int ktn = (kt + 2 < 16) ? (ktg + 2) : ktg;
#pragma unroll
            for (int nt = 0; nt < 2; nt++) {
                Bc[nt][0] = Bn[nt][0]; Bc[nt][1] = Bn[nt][1];
                int NT = 2 * ng + nt;
                size_t on = (size_t)ktn * 512 + NT * 64 + lane * 2;
                Bn[nt][0] = __ldcg((const ull*)(hHi + on));
                Bn[nt][1] = __ldcg((const ull*)(hLo + on));
            }
        }

        // epilogue operand loads (latency hides under reduce)
        const float* xs = xgbase + (size_t)s * G_ * B_;
        float xz0 = xs[(size_t)gu0 * B_ + eb];
        float xr0 = xs[(size_t)(U_ + gu0) * B_ + eb];
        float xq0 = xs[(size_t)(2 * U_ + gu0) * B_ + eb];
        float xz1 = xs[(size_t)gu1 * B_ + eb];
        float xr1 = xs[(size_t)(U_ + gu1) * B_ + eb];
        float xq1 = xs[(size_t)(2 * U_ + gu1) * B_ + eb];
        float hp0 = __ldcg(hprev + (size_t)gu0 * B_ + eb);
        float hp1 = __ldcg(hprev + (size_t)gu1 * B_ + eb);

        // ---- 4-round k-reduce. P0 = sS[0,3072), P1 = sS[3072,6144); sG aliases P1.
        float* P0 = sS;
        float* P1 = sS + 3072;
        float* sG = sS + 3072;
#define WRP(DST) do {                                                      \
            for (int m = 0; m < 3; m++)                                    \
                for (int nt = 0; nt < 2; nt++)                             \
                    for (int ci = 0; ci < 4; ci++) {                       \
                        int c = m * 16 + r0 + 8 * (ci >> 1);               \
                        int b = (2 * ng + nt) * 8 + qq * 2 + (ci & 1);     \
                        (DST)[c * 64 + b] = acc[m][nt][ci];                \
                    } } while (0)
#define ADDP(SRC) do {                                                     \
            for (int m = 0; m < 3; m++)                                    \
                for (int nt = 0; nt < 2; nt++)                             \
                    for (int ci = 0; ci < 4; ci++) {                       \
                        int c = m * 16 + r0 + 8 * (ci >> 1);               \
                        int b = (2 * ng + nt) * 8 + qq * 2 + (ci & 1);     \
                        acc[m][nt][ci] += (SRC)[c * 64 + b];               \
                    } } while (0)
        if (kg == 1) WRP(P0);
        if (kg == 3) WRP(P1);
        __syncthreads();
        if (kg == 0) ADDP(P0);
        if (kg == 2) ADDP(P1);
        __syncthreads();               // P1 dead
        if (kg == 2) WRP(P0);
        __syncthreads();
        if (kg == 0) {
#pragma unroll
            for (int m = 0; m < 3; m++)
#pragma unroll
                for (int nt = 0; nt < 2; nt++)
#pragma unroll
                    for (int ci = 0; ci < 4; ci++) {
                        int c = m * 16 + r0 + 8 * (ci >> 1);
                        int b = (2 * ng + nt) * 8 + qq * 2 + (ci & 1);
                        sG[c * SGST + b] = acc[m][nt][ci] + P0[c * 64 + b];
                    }
        }
        __syncthreads();
#undef WRP
#undef ADDP

        // ---- epilogue: two u's per thread; write fp32 d_outs + packed d_hsp ----
        {
            float hz0 = sG[cc0 * SGST + eb];
            float hr0 = sG[(16 + cc0) * SGST + eb];
            float hq0 = sG[(32 + cc0) * SGST + eb];
            float hz1 = sG[cc1 * SGST + eb];
            float hr1 = sG[(16 + cc1) * SGST + eb];
            float hq1 = sG[(32 + cc1) * SGST + eb];
            float z0 = sigf(xz0 + bz0 + hz0);
            float rr0 = sigf(xr0 + br0 + hr0);
            float hc0 = tanhf(xq0 + bq0 + rr0 * hq0);
            float h0 = z0 * hp0 + (1.0f - z0) * hc0;
            float z1 = sigf(xz1 + bz1 + hz1);
            float rr1 = sigf(xr1 + br1 + hr1);
            float hc1 = tanhf(xq1 + bq1 + rr1 * hq1);
            float h1 = z1 * hp1 + (1.0f - z1) * hc1;
            __stcg(&d_outs[dir][s][gu0][eb], h0);
            __stcg(&d_outs[dir][s][gu1][eb], h1);
            // packed word for (kp = uc*8 + kpl, b=eb): (h[2kp], h[2kp+1]) = (h0, h1)
            unsigned int hw = pack_split(h0, h1, 0);
            unsigned int lw = pack_split(h0, h1, 1);
            __stcg(&d_hsp[dir][pw][0][uc][tid], hw);
            __stcg(&d_hsp[dir][pw][1][uc][tid], lw);
        }

        // grid barrier (monotonic; 128 co-resident CTAs)
        __syncthreads();
        if (tid == 0) {
            __threadfence();
            unsigned target = nCTA * (unsigned)(s + 1);
            unsigned v = atomicAdd(&g_bar, 1u) + 1u;
            while (v < target) {
                __nanosleep(128);
                v = atomicAdd(&g_bar, 0u);
            }
            __threadfence();
        }
        __syncthreads();
    }
}

// ---------------- combine: out[b][t][u] = outs_f[t][u][b] + outs_b[T-1-t][u][b] ----------------
__global__ void k_comb(float* __restrict__ out) {
    __shared__ float sT[32][33];
    int t = blockIdx.x, u0 = blockIdx.y * 32, b0 = blockIdx.z * 32;
    int tx = threadIdx.x, ty = threadIdx.y;
#pragma unroll
    for (int i = 0; i < 4; i++) {
        int u = ty + i * 8;
        sT[u][tx] = d_outs[0][t][u0 + u][b0 + tx] + d_outs[1][T_ - 1 - t][u0 + u][b0 + tx];
    }
    __syncthreads();
#pragma unroll
    for (int i = 0; i < 4; i++) {
        int b = ty + i * 8;
        out[((size_t)(b0 + b) * T_ + t) * U_ + u0 + tx] = sT[tx][b];
    }
}

// ---------------- hidden concat ----------------
__global__ void k_hid(float* __restrict__ out) {
    __shared__ float sT[32][33];
    int u0 = blockIdx.x * 32, dir = blockIdx.y, b0 = blockIdx.z * 32;
    int tx = threadIdx.x, ty = threadIdx.y;
#pragma unroll
    for (int i = 0; i < 4; i++) {
        int u = ty + i * 8;
        sT[u][tx] = d_outs[dir][T_ - 1][u0 + u][b0 + tx];
    }
    __syncthreads();
#pragma unroll
    for (int i = 0; i < 4; i++) {
        int b = ty + i * 8;
        out[HID_OFF + (size_t)(b0 + b) * (2 * U_) + dir * U_ + u0 + tx] = sT[tx][b];
    }
}

extern "C" void kernel_launch(void* const* d_in, const int* in_sizes, int n_in,
                              void* d_out, int out_size) {
    const int*   tokens = (const int*)d_in[0];
    const float* emb    = (const float*)d_in[1];
    const float* Wf     = (const float*)d_in[2];
    const float* Uf     = (const float*)d_in[3];
    const float* bif    = (const float*)d_in[4];
    const float* bhf    = (const float*)d_in[5];
    const float* Wb     = (const float*)d_in[6];
    const float* Ub     = (const float*)d_in[7];
    const float* bib    = (const float*)d_in[8];
    const float* bhb    = (const float*)d_in[9];
    float* out = (float*)d_out;

    const int SMEM_REC = 49152 * 4 + 8192 * 4;  // 229376 B
    cudaFuncSetAttribute(k_rec, cudaFuncAttributeMaxDynamicSharedMemorySize, SMEM_REC);

    k_init<<<128, 256>>>();
    k_embed<<<T_, 256>>>(tokens, emb);
    {
        dim3 g(64, T_, 2);
        k_gemm_in<<<g, 128>>>(Wf, Wb, bif, bib);
    }
    k_rec<<<128, 512, SMEM_REC>>>(Uf, Ub, bhf, bhb);
    {
        dim3 g(T_, U_ / 32, B_ / 32);
        k_comb<<<g, dim3(32, 8)>>>(out);
    }
    {
        dim3 g(U_ / 32, 2, B_ / 32);
        k_hid<<<g, dim3(32, 8)>>>(out);
    }
    (void)in_sizes; (void)n_in; (void)out_size;
}